// round 4
// baseline (speedup 1.0000x reference)
#include <cuda_runtime.h>
#include <cuda_bf16.h>
#include <math.h>

// Cox partial-likelihood loss, N=8192, CENSORING < 0 (gate == event).
//
// O(N) via counting sort on ytime buckets, fully fused into ONE persistent
// kernel (32 blocks x 256 threads = 8192 threads, one per element, grid
// co-resident -> hand-rolled grid barrier is safe).
//
//   S_m = sum_k [ytime_k >= ytime_m] * exp(pred_k)
//       = (suffix over buckets > b_m) + (bucket-mates with yt_j >= yt_m)
//   loss = sum_m ev_m * (log S_m - pred_m) / sum_m ev_m
//
// All cross-thread accumulation is integer/fixed-point atomicAdd
// (associative) -> bitwise deterministic despite nondeterministic ordering.

#define CN     8192
#define B      4096
#define NBLK   32
#define NTHR   256
#define BPB    (B / NBLK)            // 128 buckets per block
#define BSCALE 409.6f                // B / 10.0
#define FXSCALE 8796093022208.0      // 2^43  (exp-sum fixed point)
#define INV_FX (1.0 / 8796093022208.0)
#define ASCALE 4398046511104.0       // 2^42  (loss-numerator fixed point)

__device__ unsigned int       g_cnt[B];      // zeroed in P2 (after consumption)
__device__ unsigned long long g_bsum[B];     // zeroed in P2
__device__ unsigned int       g_off[B + 1];
__device__ unsigned int       g_cur[B];
__device__ unsigned long long g_pfx[B];      // inclusive prefix of bucket sums
__device__ float              g_syt[CN];     // bucket-sorted ytime
__device__ unsigned long long g_sef[CN];     // bucket-sorted exp fixed-point
__device__ unsigned int       g_btc[NBLK];   // per-block bucket-count totals
__device__ unsigned long long g_btb[NBLK];   // per-block bucket-sum totals
__device__ unsigned long long g_acc_a = 0;   // i64 fixed-point numerator
__device__ unsigned long long g_acc_w = 0;   // event count
__device__ unsigned int       g_done  = 0;   // last-block ticket
__device__ unsigned int       g_bar   = 0;   // grid barrier arrive count
__device__ unsigned int       g_gen   = 0;   // grid barrier generation

__device__ __forceinline__ void grid_sync()
{
    __syncthreads();
    if (threadIdx.x == 0) {
        __threadfence();
        const unsigned int gen = atomicAdd(&g_gen, 0u);
        if (atomicAdd(&g_bar, 1u) == NBLK - 1) {
            g_bar = 0;
            __threadfence();
            atomicAdd(&g_gen, 1u);
        } else {
            while (atomicAdd(&g_gen, 0u) == gen) { }
        }
        __threadfence();
    }
    __syncthreads();
}

__device__ __forceinline__ int bucket_of(float yt)
{
    int b = (int)(yt * BSCALE);
    return b > (B - 1) ? (B - 1) : b;
}

__global__ __launch_bounds__(NTHR) void cox_kernel(
    const float* __restrict__ pred,
    const float* __restrict__ ytime,
    const int*   __restrict__ event,
    float*       __restrict__ out)
{
    const int t   = threadIdx.x;
    const int bid = blockIdx.x;
    const int tid = bid * NTHR + t;
    const int lane = t & 31;

    __shared__ unsigned int       s_wc[8];
    __shared__ unsigned long long s_wb[8];
    __shared__ unsigned int       s_basec;
    __shared__ unsigned long long s_baseb;
    __shared__ double             s_ra[8];
    __shared__ long long          s_rw[8];

    // ---------------- P0: exp + bucket histogram ----------------
    const float yt = ytime[tid];
    const float pr = pred[tid];
    const float e  = expf(pr);
    const unsigned long long ef = (unsigned long long)((double)e * FXSCALE);
    const int b = bucket_of(yt);

    if (tid == 0) { g_acc_a = 0ull; g_acc_w = 0ull; }  // re-arm for this call
    atomicAdd(&g_cnt[b], 1u);
    atomicAdd(&g_bsum[b], ef);

    grid_sync();

    // ---------------- P1: block-local scan of 128 buckets ----------------
    unsigned int       c  = 0, lc = 0;
    unsigned long long bs = 0, lb = 0;
    int cidx = 0;
    if (t < BPB) {
        cidx = bid * BPB + t;
        c  = g_cnt[cidx];
        bs = g_bsum[cidx];
        lc = c; lb = bs;
        #pragma unroll
        for (int o = 1; o < 32; o <<= 1) {
            const unsigned int       pc = __shfl_up_sync(0xFFFFFFFFu, lc, o);
            const unsigned long long pb = __shfl_up_sync(0xFFFFFFFFu, lb, o);
            if (lane >= o) { lc += pc; lb += pb; }
        }
        if (lane == 31) { s_wc[t >> 5] = lc; s_wb[t >> 5] = lb; }
    }
    __syncthreads();
    if (t < BPB) {
        for (int w = 0; w < (t >> 5); ++w) { lc += s_wc[w]; lb += s_wb[w]; }
        if (t == BPB - 1) { g_btc[bid] = lc; g_btb[bid] = lb; }
    }

    grid_sync();

    // ---------------- P2: block bases + final offsets/prefix, zero hist ----
    if (t < 32) {
        const unsigned int       tc = g_btc[t];
        const unsigned long long tb = g_btb[t];
        unsigned int       ic = tc;
        unsigned long long ib = tb;
        #pragma unroll
        for (int o = 1; o < 32; o <<= 1) {
            const unsigned int       pc = __shfl_up_sync(0xFFFFFFFFu, ic, o);
            const unsigned long long pb = __shfl_up_sync(0xFFFFFFFFu, ib, o);
            if (lane >= o) { ic += pc; ib += pb; }
        }
        if (t == bid) { s_basec = ic - tc; s_baseb = ib - tb; }
    }
    __syncthreads();
    if (t < BPB) {
        const unsigned int offx = s_basec + (lc - c);   // exclusive offset
        g_off[cidx] = offx;
        g_cur[cidx] = offx;
        g_pfx[cidx] = s_baseb + lb;                     // inclusive prefix
        if (cidx == B - 1) g_off[B] = s_basec + lc;
        g_cnt[cidx]  = 0u;                              // re-zero for replay
        g_bsum[cidx] = 0ull;
    }

    grid_sync();

    // ---------------- P3: counting-sort scatter ----------------
    {
        const unsigned int pos = atomicAdd(&g_cur[b], 1u);
        g_syt[pos] = yt;
        g_sef[pos] = ef;
    }

    grid_sync();

    // ---------------- P4: per-m loss term + reduction ----------------
    const int ev = event[tid];

    unsigned long long S = g_pfx[B - 1] - g_pfx[b];     // buckets strictly above
    const unsigned int lo = g_off[b], hi = g_off[b + 1];
    for (unsigned int j = lo; j < hi; ++j)
        if (g_syt[j] >= yt) S += g_sef[j];              // order-invariant u64

    const float Sf = (float)((double)S * INV_FX);
    double    a = (double)ev * ((double)logf(Sf) - (double)pr);
    long long w = (long long)ev;

    #pragma unroll
    for (int o = 16; o > 0; o >>= 1) {
        a += __shfl_xor_sync(0xFFFFFFFFu, a, o);
        w += __shfl_xor_sync(0xFFFFFFFFu, w, o);
    }
    const int wid = t >> 5;
    if (lane == 0) { s_ra[wid] = a; s_rw[wid] = w; }
    __syncthreads();
    if (t == 0) {
        double    ab = 0.0;
        long long wb = 0;
        #pragma unroll
        for (int i = 0; i < 8; ++i) { ab += s_ra[i]; wb += s_rw[i]; }
        atomicAdd(&g_acc_a, (unsigned long long)(long long)(ab * ASCALE));
        atomicAdd(&g_acc_w, (unsigned long long)wb);
        __threadfence();
        if (atomicAdd(&g_done, 1u) == NBLK - 1) {
            g_done = 0u;                                // re-arm ticket
            const long long ai = (long long)atomicAdd(&g_acc_a, 0ull);
            const long long wi = (long long)atomicAdd(&g_acc_w, 0ull);
            out[0] = (float)(((double)ai / ASCALE) / (double)wi);
        }
    }
}

extern "C" void kernel_launch(void* const* d_in, const int* in_sizes, int n_in,
                              void* d_out, int out_size)
{
    const float* pred  = (const float*)d_in[0];
    const float* ytime = (const float*)d_in[1];
    const int*   event = (const int*)d_in[2];
    float*       out   = (float*)d_out;

    cox_kernel<<<NBLK, NTHR>>>(pred, ytime, event, out);
}